// round 17
// baseline (speedup 1.0000x reference)
#include <cuda_runtime.h>
#include <cuda_bf16.h>

// BERTLatticeEmbedding: ragged segment mean-pool.
// hidden [B,S,H] f32, word_ids [B,S] int32 (sorted per row),
// out [B,T,H] f32. B=64, S=512, H=768, T=400.
//
// R13: SINGLE kernel, block = (b, 8 words), 8 warps. Warp 0 computes all 9
// segment boundaries with a 2-level warp-ballot search over the L2-hot
// word_ids row (probe load -> 9 ballots -> 5 batched chunk loads -> 5
// ballots) into SMEM; one __syncthreads; then the proven R9 payload:
// warp = (word-pair, half-row), 6-LDG.128 bursts, warp-uniform predicated
// A/B accumulation, __ldcs reads, __stcs stores.

#define B_DIM 64
#define S_DIM 512
#define H_DIM 768
#define T_DIM 400
#define H4    (H_DIM / 4)       // 192 float4 per row
#define HALF4 (H4 / 2)          // 96 float4 per half-row
#define TPB   256               // 8 warps
#define BLOCKS_PER_B 50         // 8 words per block, 400 words... T=400/8

__device__ __forceinline__ void f4add(float4& a, const float4 v) {
    a.x += v.x; a.y += v.y; a.z += v.z; a.w += v.w;
}
__device__ __forceinline__ void f4scale(float4& a, const float s) {
    a.x *= s; a.y *= s; a.z *= s; a.w *= s;
}

__global__ __launch_bounds__(TPB) void pool_kernel(
    const float* __restrict__ hidden,
    const int* __restrict__ word_ids,
    float* __restrict__ out)
{
    __shared__ int s_b[9];      // start[wbase .. wbase+8]

    const int bid    = blockIdx.x;
    const int b      = bid / BLOCKS_PER_B;
    const int blk_in = bid - b * BLOCKS_PER_B;
    const int wbase  = blk_in * 8;
    const int tid    = threadIdx.x;
    const int warp   = tid >> 5;
    const int lane   = tid & 31;

    const int* __restrict__ row = word_ids + b * S_DIM;
    const unsigned FULL = 0xffffffffu;

    if (warp == 0) {
        // Level 1: lane i probes max of 16-element chunk i (row sorted).
        const int pv = __ldg(row + lane * 16 + 15);
        int c[9];
        #pragma unroll
        for (int t = 0; t < 9; ++t)
            c[t] = __popc(__ballot_sync(FULL, pv < wbase + t));   // warp-uniform

        // Level 2: 5 rounds, half-warp per target; loads hoisted & batched.
        const int hw = lane >> 4;     // 0: even target, 1: odd target
        const int li = lane & 15;
        int v[5];
        #pragma unroll
        for (int r = 0; r < 5; ++r) {
            int t  = 2 * r + hw; if (t > 8) t = 8;
            int cc = c[t];
            v[r] = (cc < 32) ? __ldg(row + cc * 16 + li) : 0x7fffffff;
        }
        #pragma unroll
        for (int r = 0; r < 5; ++r) {
            int t = 2 * r + hw; if (t > 8) t = 8;
            const unsigned m = __ballot_sync(FULL, v[r] < wbase + t);
            if (lane == 0) {
                const int tLo = 2 * r;
                const int cLo = c[tLo];
                s_b[tLo] = (cLo < 32) ? cLo * 16 + __popc(m & 0xFFFFu) : S_DIM;
                if (tLo + 1 <= 8) {
                    const int cHi = c[tLo + 1];
                    s_b[tLo + 1] = (cHi < 32) ? cHi * 16 + __popc(m >> 16) : S_DIM;
                }
            }
        }
    }
    __syncthreads();

    const int pair = warp >> 1;               // 0..3
    const int half = warp & 1;
    const int w0   = wbase + pair * 2;
    const int off  = half * HALF4 + lane;

    const int s0 = s_b[pair * 2];
    const int s1 = s_b[pair * 2 + 1];
    const int s2 = s_b[pair * 2 + 2];

    const float4* __restrict__ hin =
        reinterpret_cast<const float4*>(hidden + (size_t)b * S_DIM * H_DIM) + off;

    const float4 Z = make_float4(0.f, 0.f, 0.f, 0.f);
    float4 A0 = Z, A1 = Z, A2 = Z;   // word w0
    float4 B0 = Z, B1 = Z, B2 = Z;   // word w0+1

    // Combined contiguous piece range [s0, s2); warp-uniform predicates.
    for (int s = s0; s < s2; s += 2) {
        const float4* q = hin + (size_t)s * H4;
        const bool has1 = (s + 1 < s2);
        float4 v0 = __ldcs(q);
        float4 v1 = __ldcs(q + 32);
        float4 v2 = __ldcs(q + 64);
        float4 u0, u1, u2;
        if (has1) {
            u0 = __ldcs(q + H4);
            u1 = __ldcs(q + H4 + 32);
            u2 = __ldcs(q + H4 + 64);
        }
        if (s < s1) { f4add(A0, v0); f4add(A1, v1); f4add(A2, v2); }
        else        { f4add(B0, v0); f4add(B1, v1); f4add(B2, v2); }
        if (has1) {
            if (s + 1 < s1) { f4add(A0, u0); f4add(A1, u1); f4add(A2, u2); }
            else            { f4add(B0, u0); f4add(B1, u1); f4add(B2, u2); }
        }
    }

    const int cA = s1 - s0;
    const int cB = s2 - s1;
    const float invA = 1.0f / (float)(cA > 0 ? cA : 1);
    const float invB = 1.0f / (float)(cB > 0 ? cB : 1);
    f4scale(A0, invA); f4scale(A1, invA); f4scale(A2, invA);
    f4scale(B0, invB); f4scale(B1, invB); f4scale(B2, invB);

    float4* __restrict__ opA =
        reinterpret_cast<float4*>(out + ((size_t)b * T_DIM + w0) * H_DIM) + off;
    float4* __restrict__ opB = opA + H4;
    __stcs(opA,      A0);
    __stcs(opA + 32, A1);
    __stcs(opA + 64, A2);
    __stcs(opB,      B0);
    __stcs(opB + 32, B1);
    __stcs(opB + 64, B2);
}

extern "C" void kernel_launch(void* const* d_in, const int* in_sizes, int n_in,
                              void* d_out, int out_size)
{
    const float* hidden   = (const float*)d_in[0];
    const int*   word_ids = (const int*)d_in[1];
    float* out = (float*)d_out;

    pool_kernel<<<B_DIM * BLOCKS_PER_B, TPB>>>(hidden, word_ids, out);  // 3200
}